// round 1
// baseline (speedup 1.0000x reference)
#include <cuda_runtime.h>

// Stochastic-LIF eval-mode scan.
// x: [B=32, T=128, N=8192] f32, o: same shape.
// Recurrence per (b, n): u = 0.5*u + x_t; o = (u > 1); u = o ? 0 : u.
// Each thread handles one float4 (4 adjacent n) across all 128 time steps.

static constexpr int B = 32;
static constexpr int T = 128;
static constexpr int N = 8192;
static constexpr int NV = N / 4;          // float4 columns per (b, t) row: 2048
static constexpr int CHAINS = B * NV;     // 65536 threads

__global__ void __launch_bounds__(256, 8)
lif_scan_kernel(const float4* __restrict__ x, float4* __restrict__ o) {
    const int idx = blockIdx.x * blockDim.x + threadIdx.x;   // 0 .. CHAINS-1
    const int b = idx / NV;
    const int n = idx % NV;

    const float4* __restrict__ xp = x + (size_t)b * T * NV + n;
    float4* __restrict__ op       = o + (size_t)b * T * NV + n;

    float ux = 0.f, uy = 0.f, uz = 0.f, uw = 0.f;

    #pragma unroll 4
    for (int t = 0; t < T; ++t) {
        float4 xv = xp[(size_t)t * NV];

        ux = fmaf(0.5f, ux, xv.x);
        uy = fmaf(0.5f, uy, xv.y);
        uz = fmaf(0.5f, uz, xv.z);
        uw = fmaf(0.5f, uw, xv.w);

        float4 ov;
        ov.x = (ux > 1.0f) ? 1.0f : 0.0f;
        ov.y = (uy > 1.0f) ? 1.0f : 0.0f;
        ov.z = (uz > 1.0f) ? 1.0f : 0.0f;
        ov.w = (uw > 1.0f) ? 1.0f : 0.0f;

        // hard reset by multiply: u *= (1 - o)  ==  u = spiked ? 0 : u
        ux = (ux > 1.0f) ? 0.0f : ux;
        uy = (uy > 1.0f) ? 0.0f : uy;
        uz = (uz > 1.0f) ? 0.0f : uz;
        uw = (uw > 1.0f) ? 0.0f : uw;

        op[(size_t)t * NV] = ov;
    }
}

extern "C" void kernel_launch(void* const* d_in, const int* in_sizes, int n_in,
                              void* d_out, int out_size) {
    const float4* x = (const float4*)d_in[0];
    float4* o = (float4*)d_out;
    (void)in_sizes; (void)n_in; (void)out_size;

    const int threads = 256;
    const int blocks = CHAINS / threads;   // 256
    lif_scan_kernel<<<blocks, threads>>>(x, o);
}

// round 3
// speedup vs baseline: 1.0230x; 1.0230x over previous
#include <cuda_runtime.h>

// Stochastic-LIF eval-mode scan.
// x: [B=32, T=128, N=8192] f32, o: same shape.
// Recurrence per (b, n): u = 0.5*u + x_t; o = (u > 1); u = o ? 0 : u.
// Each thread handles one float4 (4 adjacent n) across all 128 time steps.
// T is processed in chunks of 8 with all 8 LDG.128 issued up-front (MLP=8)
// before the sequential u-chain consumes them.

static constexpr int B = 32;
static constexpr int T = 128;
static constexpr int N = 8192;
static constexpr int NV = N / 4;          // float4 columns per (b, t) row: 2048
static constexpr int CHAINS = B * NV;     // 65536 threads
static constexpr int CH = 8;              // time-chunk (prefetch depth)

__global__ void __launch_bounds__(256)
lif_scan_kernel(const float4* __restrict__ x, float4* __restrict__ o) {
    const int idx = blockIdx.x * blockDim.x + threadIdx.x;   // 0 .. CHAINS-1
    const int b = idx / NV;
    const int n = idx % NV;

    const float4* __restrict__ xp = x + (size_t)b * T * NV + n;
    float4* __restrict__ op       = o + (size_t)b * T * NV + n;

    float ux = 0.f, uy = 0.f, uz = 0.f, uw = 0.f;

    #pragma unroll 1
    for (int t0 = 0; t0 < T; t0 += CH) {
        // Phase 1: batch 8 independent 16B loads (front-loaded MLP)
        float4 xv[CH];
        #pragma unroll
        for (int i = 0; i < CH; ++i) {
            xv[i] = xp[(size_t)(t0 + i) * NV];
        }

        // Phase 2: sequential LIF chain; store each result immediately
        #pragma unroll
        for (int i = 0; i < CH; ++i) {
            ux = fmaf(0.5f, ux, xv[i].x);
            uy = fmaf(0.5f, uy, xv[i].y);
            uz = fmaf(0.5f, uz, xv[i].z);
            uw = fmaf(0.5f, uw, xv[i].w);

            float4 ov;
            ov.x = (ux > 1.0f) ? 1.0f : 0.0f;
            ov.y = (uy > 1.0f) ? 1.0f : 0.0f;
            ov.z = (uz > 1.0f) ? 1.0f : 0.0f;
            ov.w = (uw > 1.0f) ? 1.0f : 0.0f;

            ux = (ux > 1.0f) ? 0.0f : ux;
            uy = (uy > 1.0f) ? 0.0f : uy;
            uz = (uz > 1.0f) ? 0.0f : uz;
            uw = (uw > 1.0f) ? 0.0f : uw;

            op[(size_t)(t0 + i) * NV] = ov;
        }
    }
}

extern "C" void kernel_launch(void* const* d_in, const int* in_sizes, int n_in,
                              void* d_out, int out_size) {
    const float4* x = (const float4*)d_in[0];
    float4* o = (float4*)d_out;
    (void)in_sizes; (void)n_in; (void)out_size;

    const int threads = 256;
    const int blocks = CHAINS / threads;   // 256
    lif_scan_kernel<<<blocks, threads>>>(x, o);
}

// round 4
// speedup vs baseline: 1.1172x; 1.0921x over previous
#include <cuda_runtime.h>

// Stochastic-LIF eval-mode scan.
// x: [B=32, T=128, N=8192] f32, o: same shape.
// Recurrence per (b, n): u = 0.5*u + x_t; o = (u > 1); u = o ? 0 : u.
// Each thread owns one float4 (4 adjacent n) across all 128 time steps.
// T processed in chunks of 8; the 8 independent LDG.128 are issued via
// asm volatile so ptxas CANNOT sink them to their uses (true MLP=8).

static constexpr int B = 32;
static constexpr int T = 128;
static constexpr int N = 8192;
static constexpr int NV = N / 4;          // float4 columns per (b, t) row: 2048
static constexpr int CHAINS = B * NV;     // 65536 threads
static constexpr int CH = 8;              // time-chunk (prefetch depth)

__global__ void __launch_bounds__(256)
lif_scan_kernel(const float4* __restrict__ x, float4* __restrict__ o) {
    const int idx = blockIdx.x * blockDim.x + threadIdx.x;   // 0 .. CHAINS-1
    const int b = idx >> 11;          // / NV
    const int n = idx & (NV - 1);     // % NV

    const float4* __restrict__ xp = x + (size_t)b * T * NV + n;
    float4* __restrict__ op       = o + (size_t)b * T * NV + n;

    float ux = 0.f, uy = 0.f, uz = 0.f, uw = 0.f;

    #pragma unroll 1
    for (int t0 = 0; t0 < T; t0 += CH) {
        // Phase 1: 8 independent streaming loads, order-pinned by asm volatile.
        float xr[CH][4];
        #pragma unroll
        for (int i = 0; i < CH; ++i) {
            const float4* p = xp + (size_t)(t0 + i) * NV;
            asm volatile("ld.global.cs.v4.f32 {%0,%1,%2,%3}, [%4];"
                         : "=f"(xr[i][0]), "=f"(xr[i][1]),
                           "=f"(xr[i][2]), "=f"(xr[i][3])
                         : "l"(p));
        }

        // Phase 2: sequential LIF chain; streaming store per step.
        #pragma unroll
        for (int i = 0; i < CH; ++i) {
            ux = fmaf(0.5f, ux, xr[i][0]);
            uy = fmaf(0.5f, uy, xr[i][1]);
            uz = fmaf(0.5f, uz, xr[i][2]);
            uw = fmaf(0.5f, uw, xr[i][3]);

            float ox = (ux > 1.0f) ? 1.0f : 0.0f;
            float oy = (uy > 1.0f) ? 1.0f : 0.0f;
            float oz = (uz > 1.0f) ? 1.0f : 0.0f;
            float ow = (uw > 1.0f) ? 1.0f : 0.0f;

            ux = (ux > 1.0f) ? 0.0f : ux;
            uy = (uy > 1.0f) ? 0.0f : uy;
            uz = (uz > 1.0f) ? 0.0f : uz;
            uw = (uw > 1.0f) ? 0.0f : uw;

            float4* q = op + (size_t)(t0 + i) * NV;
            asm volatile("st.global.cs.v4.f32 [%0], {%1,%2,%3,%4};"
                         :: "l"(q), "f"(ox), "f"(oy), "f"(oz), "f"(ow)
                         : "memory");
        }
    }
}

extern "C" void kernel_launch(void* const* d_in, const int* in_sizes, int n_in,
                              void* d_out, int out_size) {
    const float4* x = (const float4*)d_in[0];
    float4* o = (float4*)d_out;
    (void)in_sizes; (void)n_in; (void)out_size;

    const int threads = 256;
    const int blocks = CHAINS / threads;   // 256
    lif_scan_kernel<<<blocks, threads>>>(x, o);
}